// round 2
// baseline (speedup 1.0000x reference)
#include <cuda_runtime.h>

// BinaryTree path-probability (hierarchical softmax along one root->leaf path):
//   x      = W[v_j + 2^20 - 1]                      (128 fp32, leaf row)
//   path_l = ((u_k + 2^20) >> (20 - l)) - 1         for l = 0..20
//   out    = prod_l sigmoid( dot(W[path_l], x) )
//
// Latency-bound micro-kernel: one warp, lane i owns the float4 slice
// [4i, 4i+4) of every row. The 22 row loads are mutually independent and
// front-batched by ptxas (MLP ~22) -> a single DRAM round trip after the
// index-load round trip.

#define BT_DEPTH 20
#define BT_NDIMS 128

__global__ void __launch_bounds__(32, 1)
binary_tree_path_prob_kernel(const float* __restrict__ W,
                             const int* __restrict__ v_j_idx,
                             const int* __restrict__ u_k_idx,
                             float* __restrict__ out) {
    const int lane = threadIdx.x;  // 0..31

    // Both scalar index loads issue immediately (one shared round trip).
    const int v = *v_j_idx;
    const int u = *u_k_idx;

    const long long leaf_off = (1LL << BT_DEPTH) - 1;  // 1,048,575

    // Leaf row x: this lane's float4 slice.
    const float4* xrow =
        reinterpret_cast<const float4*>(W + (long long)(v + leaf_off) * BT_NDIMS);
    const float4 x4 = __ldg(&xrow[lane]);

    // Path rows: all 21 loads independent of each other and of the x load.
    const unsigned t = (unsigned)u + (1u << BT_DEPTH);  // leaf tree-index + 1

    float partial[BT_DEPTH + 1];
#pragma unroll
    for (int l = 0; l <= BT_DEPTH; ++l) {
        const long long node = (long long)(t >> (BT_DEPTH - l)) - 1;
        const float4* wrow =
            reinterpret_cast<const float4*>(W + node * BT_NDIMS);
        const float4 w4 = __ldg(&wrow[lane]);
        partial[l] = w4.x * x4.x + w4.y * x4.y + w4.z * x4.z + w4.w * x4.w;
    }

    // 21 butterfly reductions (independent shfl chains, fully pipelined).
    // Accumulate prod(1 + e^{-s}) and take a single reciprocal at the end:
    //   prod sigmoid(s_l) = 1 / prod(1 + exp(-s_l))
    float denom = 1.0f;
#pragma unroll
    for (int l = 0; l <= BT_DEPTH; ++l) {
        float s = partial[l];
#pragma unroll
        for (int off = 16; off > 0; off >>= 1)
            s += __shfl_xor_sync(0xFFFFFFFFu, s, off);
        denom *= 1.0f + __expf(-s);
    }

    if (lane == 0) out[0] = 1.0f / denom;
}

extern "C" void kernel_launch(void* const* d_in, const int* in_sizes, int n_in,
                              void* d_out, int out_size) {
    const float* W     = (const float*)d_in[0];
    const int*   v_idx = (const int*)d_in[1];
    const int*   u_idx = (const int*)d_in[2];
    float*       out   = (float*)d_out;

    binary_tree_path_prob_kernel<<<1, 32>>>(W, v_idx, u_idx, out);
}